// round 2
// baseline (speedup 1.0000x reference)
#include <cuda_runtime.h>
#include <math.h>

#define T      128
#define F      512
#define H      1024
#define RZ     1536          // F + H
#define NCG    16            // column groups
#define NRG    8             // row groups
#define CPB    64            // cols per CTA
#define RPB    192           // rows per CTA
#define NTH    256
#define DEPTH  3
#define TILE_FLOATS (RPB * CPB)           // 12288
#define SMEM_FLOATS (DEPTH * TILE_FLOATS + RPB + NTH)

__device__ float    g_h[T * H];
__device__ float    g_part[T * NCG * NRG * CPB];   // per-step partial sums
__device__ unsigned g_cnt[T * NCG];                // arrivals per (t, colgroup)
__device__ unsigned g_step[T];                     // reducers done per step

__global__ void pg_init() {
    for (int i = threadIdx.x; i < T * NCG; i += blockDim.x) g_cnt[i] = 0u;
    for (int i = threadIdx.x; i < T; i += blockDim.x) g_step[i] = 0u;
}

__device__ __forceinline__ unsigned ld_acq(const unsigned* p) {
    unsigned v;
    asm volatile("ld.global.acquire.gpu.u32 %0, [%1];" : "=r"(v) : "l"(p) : "memory");
    return v;
}
__device__ __forceinline__ void red_rel(unsigned* p, unsigned v) {
    asm volatile("red.release.gpu.global.add.u32 [%0], %1;" :: "l"(p), "r"(v) : "memory");
}
__device__ __forceinline__ void cp_async16(unsigned saddr, const void* gaddr) {
    asm volatile("cp.async.cg.shared.global [%0], [%1], 16;" :: "r"(saddr), "l"(gaddr));
}
__device__ __forceinline__ void cp_commit() {
    asm volatile("cp.async.commit_group;");
}
__device__ __forceinline__ void cp_wait2() {
    asm volatile("cp.async.wait_group 2;");
}

// Issue one 192x64 fp32 tile (48KB) for step t into smem ring slot t%DEPTH.
// 3072 x 16B transfers; warp covers 2 contiguous 256B rows -> fully coalesced.
__device__ __forceinline__ void issue_tile(const float* __restrict__ Ws,
                                           int t, int rg, int cg,
                                           unsigned sbase, int tid) {
    const float* gbase = Ws + ((size_t)t * RZ + rg * RPB) * H + cg * CPB;
    unsigned sb = sbase + (unsigned)(t % DEPTH) * (TILE_FLOATS * 4);
#pragma unroll
    for (int it = 0; it < 12; ++it) {
        int idx = tid + it * NTH;          // 0..3071
        int row = idx >> 4;
        int seg = idx & 15;
        cp_async16(sb + (unsigned)(row * 256 + seg * 16),
                   (const void*)(gbase + (size_t)row * H + seg * 4));
    }
}

__global__ void __launch_bounds__(NTH, 1) pg_rnn(
    const float* __restrict__ x,    // (1, T, F)
    const float* __restrict__ h0,   // (H,)
    const float* __restrict__ Ws,   // (T, RZ, H)
    const float* __restrict__ bs,   // (T, H)
    const float* __restrict__ Wo,   // (H, 2)
    const float* __restrict__ bo,   // (2,)
    float* __restrict__ out)        // [actors(2), h_final(H)]
{
    extern __shared__ float sm[];
    float* s_w   = sm;                            // DEPTH * 12288
    float* s_z   = sm + DEPTH * TILE_FLOATS;      // 192
    float* s_red = s_z + RPB;                     // 256

    const int tid  = threadIdx.x;
    const int cg   = blockIdx.x & (NCG - 1);
    const int rg   = blockIdx.x >> 4;
    const int c    = tid & (CPB - 1);             // 0..63
    const int gg   = tid >> 6;                    // 0..3  (48-row subgroup)
    const bool dep = (rg * RPB + RPB > F);        // tile touches h rows?

    unsigned sbase = (unsigned)__cvta_generic_to_shared(s_w);

    // prologue: fill the ring
#pragma unroll
    for (int d = 0; d < DEPTH; ++d) {
        issue_tile(Ws, d, rg, cg, sbase, tid);
        cp_commit();
    }

    for (int t = 0; t < T; ++t) {
        cp_wait2();                    // oldest tile landed (my groups)

        // acquire previous hidden state (only row-groups overlapping h rows)
        if (dep && t > 0 && tid == 0) {
            while (ld_acq(&g_step[t - 1]) != (unsigned)NCG) { }
        }
        __syncthreads();               // tile visible + h acquired, CTA-wide

        // stage z slice for this CTA's rows
        if (tid < RPB) {
            int zr = rg * RPB + tid;
            float v;
            if (zr < F)      v = x[t * F + zr];
            else if (t == 0) v = h0[zr - F];
            else             v = g_h[(t - 1) * H + (zr - F)];
            s_z[tid] = v;
        }
        __syncthreads();

        // 48 FMAs per thread from smem (conflict-free)
        const float* wb = s_w + (t % DEPTH) * TILE_FLOATS + gg * (48 * CPB) + c;
        const float* zb = s_z + gg * 48;
        float a0 = 0.f, a1 = 0.f, a2 = 0.f, a3 = 0.f;
#pragma unroll
        for (int k = 0; k < 48; k += 4) {
            a0 = fmaf(zb[k + 0], wb[(k + 0) * CPB], a0);
            a1 = fmaf(zb[k + 1], wb[(k + 1) * CPB], a1);
            a2 = fmaf(zb[k + 2], wb[(k + 2) * CPB], a2);
            a3 = fmaf(zb[k + 3], wb[(k + 3) * CPB], a3);
        }
        s_red[tid] = (a0 + a1) + (a2 + a3);
        __syncthreads();               // all done reading s_w slot -> reusable

        // prefetch step t+DEPTH into the slot just freed
        if (t + DEPTH < T) issue_tile(Ws, t + DEPTH, rg, cg, sbase, tid);
        cp_commit();                   // always commit to keep group count aligned

        // write this CTA's 64 partial sums
        if (tid < CPB) {
            float p = s_red[tid] + s_red[tid + 64] + s_red[tid + 128] + s_red[tid + 192];
            g_part[((size_t)(t * NCG + cg) * NRG + rg) * CPB + tid] = p;
            __threadfence();
        }
        __syncthreads();
        if (tid == 0) red_rel(&g_cnt[t * NCG + cg], 1u);

        // reducer: rg 7 gathers 8 partials, applies bias+tanh, releases step
        if (rg == NRG - 1) {
            if (tid == 0) {
                while (ld_acq(&g_cnt[t * NCG + cg]) != (unsigned)NRG) { }
            }
            __syncthreads();
            if (tid < CPB) {
                const float* pp = g_part + (size_t)(t * NCG + cg) * NRG * CPB + tid;
                float s = 0.f;
#pragma unroll
                for (int r = 0; r < NRG; ++r) s += pp[r * CPB];
                int col = cg * CPB + tid;
                float hv = tanhf(s + bs[t * H + col]);
                g_h[t * H + col] = hv;
                if (t == T - 1) out[2 + col] = hv;
                __threadfence();
            }
            __syncthreads();
            if (tid == 0) red_rel(&g_step[t], 1u);
        }
    }

    // actor head: CTA 0 (free-runner, already idle)
    if (blockIdx.x == 0) {
        if (tid == 0) {
            while (ld_acq(&g_step[T - 1]) != (unsigned)NCG) { }
        }
        __syncthreads();

        const float* hf = g_h + (size_t)(T - 1) * H;
        float r0 = 0.f, r1 = 0.f;
        for (int i = tid; i < H; i += NTH) {
            float hv = hf[i];
            r0 = fmaf(hv, Wo[2 * i + 0], r0);
            r1 = fmaf(hv, Wo[2 * i + 1], r1);
        }
#pragma unroll
        for (int o = 16; o > 0; o >>= 1) {
            r0 += __shfl_xor_sync(0xffffffffu, r0, o);
            r1 += __shfl_xor_sync(0xffffffffu, r1, o);
        }
        const int lane = tid & 31, warp = tid >> 5;
        if (lane == 0) { s_red[warp] = r0; s_red[8 + warp] = r1; }
        __syncthreads();
        if (tid == 0) {
            float s0 = 0.f, s1 = 0.f;
#pragma unroll
            for (int w = 0; w < 8; ++w) { s0 += s_red[w]; s1 += s_red[8 + w]; }
            out[0] = s0 + bo[0];
            out[1] = s1 + bo[1];
        }
    }
}

extern "C" void kernel_launch(void* const* d_in, const int* in_sizes, int n_in,
                              void* d_out, int out_size) {
    const float* x  = (const float*)d_in[0];
    const float* h0 = (const float*)d_in[1];
    const float* Ws = (const float*)d_in[2];
    const float* bs = (const float*)d_in[3];
    const float* Wo = (const float*)d_in[4];
    const float* bo = (const float*)d_in[5];
    float* out = (float*)d_out;

    static bool attr_set = false;
    if (!attr_set) {
        cudaFuncSetAttribute(pg_rnn, cudaFuncAttributeMaxDynamicSharedMemorySize,
                             SMEM_FLOATS * 4);
        attr_set = true;
    }

    pg_init<<<1, 256>>>();
    pg_rnn<<<NCG * NRG, NTH, SMEM_FLOATS * 4>>>(x, h0, Ws, bs, Wo, bo, out);
}

// round 3
// speedup vs baseline: 1.4170x; 1.4170x over previous
#include <cuda_runtime.h>
#include <math.h>

#define T      128
#define F      512
#define H      1024
#define RZ     1536
#define CPB    8            // cols per CTA in sequential phase
#define NC     128          // CTAs in sequential phase
#define NTH2   384          // 8 consumer warps + 4 producer warps
#define D      6            // smem ring depth (steps)
#define SLOT_BYTES (H * CPB * 4)      // 32 KB
#define SLOT_WORDS (H * CPB)

__device__ float    g_u[T * H];      // precomputed x-part (+bias)
__device__ float    g_h[T * H];      // hidden states
__device__ unsigned g_cnt[T];        // per-step release counters (target 1024)

__global__ void pg_init() {
    for (int i = threadIdx.x; i < T; i += blockDim.x) g_cnt[i] = 0u;
}

__device__ __forceinline__ unsigned ld_acq(const unsigned* p) {
    unsigned v;
    asm volatile("ld.global.acquire.gpu.u32 %0, [%1];" : "=r"(v) : "l"(p) : "memory");
    return v;
}
__device__ __forceinline__ void red_rel(unsigned* p, unsigned v) {
    asm volatile("red.release.gpu.global.add.u32 [%0], %1;" :: "l"(p), "r"(v) : "memory");
}
__device__ __forceinline__ void cp_async16(unsigned saddr, const void* gaddr) {
    asm volatile("cp.async.cg.shared.global [%0], [%1], 16;" :: "r"(saddr), "l"(gaddr));
}
__device__ __forceinline__ void cp_commit() { asm volatile("cp.async.commit_group;"); }
template<int N> __device__ __forceinline__ void cp_waitg() {
    asm volatile("cp.async.wait_group %0;" :: "n"(N));
}
__device__ __forceinline__ void bar1() {      // consumer-only barrier (256 threads)
    asm volatile("bar.sync 1, 256;" ::: "memory");
}

// ---------------- Phase 1: u[t] = x_t @ Wx_t + b_t  (fully parallel) -----------
__global__ void __launch_bounds__(256, 1) pg_xpart(
    const float* __restrict__ x, const float* __restrict__ Ws,
    const float* __restrict__ bs)
{
    const int t   = blockIdx.x >> 3;
    const int cg  = blockIdx.x & 7;          // 8 col groups of 128
    const int tid = threadIdx.x;

    __shared__ float sx[F];
    __shared__ float sacc[256];
    sx[tid]       = x[t * F + tid];
    sx[tid + 256] = x[t * F + tid + 256];
    __syncthreads();

    const int c    = cg * 128 + (tid & 127);
    const int half = tid >> 7;
    const float* wp = Ws + ((size_t)t * RZ + half * 256) * H + c;
    const float* zz = sx + half * 256;

    float a0 = 0.f, a1 = 0.f, a2 = 0.f, a3 = 0.f;
#pragma unroll 8
    for (int r = 0; r < 256; r += 4) {
        a0 = fmaf(zz[r + 0], wp[(size_t)(r + 0) * H], a0);
        a1 = fmaf(zz[r + 1], wp[(size_t)(r + 1) * H], a1);
        a2 = fmaf(zz[r + 2], wp[(size_t)(r + 2) * H], a2);
        a3 = fmaf(zz[r + 3], wp[(size_t)(r + 3) * H], a3);
    }
    sacc[tid] = (a0 + a1) + (a2 + a3);
    __syncthreads();
    if (tid < 128) {
        int col = cg * 128 + tid;
        g_u[t * H + col] = sacc[tid] + sacc[tid + 128] + bs[t * H + col];
    }
}

// ---------------- Phase 2: sequential recurrence, warp-specialized ------------
__global__ void __launch_bounds__(NTH2, 1) pg_seq(
    const float* __restrict__ h0, const float* __restrict__ Ws,
    const float* __restrict__ Wo, const float* __restrict__ bo,
    float* __restrict__ out)
{
    extern __shared__ char sm[];
    float* s_w   = (float*)sm;                       // D slots of 32KB
    float* s_red = (float*)(sm + D * SLOT_BYTES);    // 64 floats
    int*   s_full = (int*)(s_red + 64);              // D counters
    volatile int* s_consumed = (volatile int*)(s_full + D);

    const int tid = threadIdx.x;
    const int cg  = blockIdx.x;                      // col group: cols cg*8..cg*8+7
    unsigned sbase = (unsigned)__cvta_generic_to_shared(s_w);

    if (tid == 0) {
        for (int i = 0; i < D; ++i) s_full[i] = 0;
        *s_consumed = 0;
    }
    __syncthreads();                                 // only full-CTA sync in kernel

    if (tid >= 256) {
        // ---------------- producers: stream Wh tiles, paced by slot recycling ----
        const int pt = tid - 256;                    // 0..127
        const float* gcols = Ws + (size_t)F * H + (size_t)cg * CPB;
        for (int t = 0; t < T; ++t) {
            const int lim = t - (D - 1);
            while (*s_consumed < lim) { }            // slot free?
            unsigned sb = sbase + (unsigned)(t % D) * SLOT_BYTES;
            const float* gb = gcols + (size_t)t * RZ * H;
#pragma unroll
            for (int i = 0; i < 16; ++i) {
                int n   = i * 128 + pt;              // 0..2047
                int row = n >> 1;
                int cc  = n & 1;
                unsigned soff = sb + (unsigned)(row * 32 + ((cc ^ ((row >> 2) & 1)) << 4));
                cp_async16(soff, (const void*)(gb + (size_t)row * H + cc * 4));
            }
            cp_commit();
            if (t >= 2) {                            // group t-2 has landed
                cp_waitg<2>();
                __threadfence_block();
                atomicAdd(&s_full[(t - 2) % D], 1);
            }
        }
        cp_waitg<1>(); __threadfence_block(); atomicAdd(&s_full[(T - 2) % D], 1);
        cp_waitg<0>(); __threadfence_block(); atomicAdd(&s_full[(T - 1) % D], 1);
    } else {
        // ---------------- consumers: the recurrence ----------------
        const int w = tid >> 5, l = tid & 31;
        for (int t = 0; t < T; ++t) {
            const int slot = t % D;

            float uval = 0.f;
            if (tid < 8) uval = __ldg(&g_u[t * H + cg * CPB + tid]);  // off-chain prefetch

            if (tid == 0) {
                if (t > 0) while (ld_acq(&g_cnt[t - 1]) != 1024u) { }
                while (((volatile int*)s_full)[slot] != 128) { }
            }
            bar1();                                  // h + tile visible CTA-wide

            const float* hp    = (t == 0) ? h0 : (g_h + (size_t)(t - 1) * H);
            const float* wslot = s_w + slot * SLOT_WORDS;

            float acc[8];
#pragma unroll
            for (int j = 0; j < 8; ++j) acc[j] = 0.f;

#pragma unroll
            for (int i = 0; i < 4; ++i) {
                int r = w * 128 + i * 32 + l;
                float zv = hp[r];
                int sw = (r >> 2) & 1;
                float4 c0 = *(const float4*)(wslot + r * 8 + sw * 4);        // cols 0-3
                float4 c1 = *(const float4*)(wslot + r * 8 + (sw ^ 1) * 4);  // cols 4-7
                acc[0] = fmaf(zv, c0.x, acc[0]); acc[1] = fmaf(zv, c0.y, acc[1]);
                acc[2] = fmaf(zv, c0.z, acc[2]); acc[3] = fmaf(zv, c0.w, acc[3]);
                acc[4] = fmaf(zv, c1.x, acc[4]); acc[5] = fmaf(zv, c1.y, acc[5]);
                acc[6] = fmaf(zv, c1.z, acc[6]); acc[7] = fmaf(zv, c1.w, acc[7]);
            }
#pragma unroll
            for (int off = 16; off >= 1; off >>= 1)
#pragma unroll
                for (int j = 0; j < 8; ++j)
                    acc[j] += __shfl_xor_sync(0xffffffffu, acc[j], off);
            if (l == 0) {
#pragma unroll
                for (int j = 0; j < 8; ++j) s_red[w * 8 + j] = acc[j];
            }
            bar1();                                  // slot fully consumed

            if (tid == 0) {                          // recycle slot for producers
                s_full[slot] = 0;
                __threadfence_block();
                *s_consumed = t + 1;
            }
            if (tid < 8) {
                float s = uval;
#pragma unroll
                for (int ww = 0; ww < 8; ++ww) s += s_red[ww * 8 + tid];
                float hv = tanhf(s);
                int col = cg * CPB + tid;
                g_h[(size_t)t * H + col] = hv;
                if (t == T - 1) out[2 + col] = hv;
                red_rel(&g_cnt[t], 1u);              // release sequence -> target 1024
            }
        }

        // ---------------- actor head (block 0 consumers) ----------------
        if (cg == 0) {
            if (tid == 0) while (ld_acq(&g_cnt[T - 1]) != 1024u) { }
            bar1();
            const float* hf = g_h + (size_t)(T - 1) * H;
            float r0 = 0.f, r1 = 0.f;
            for (int i = tid; i < H; i += 256) {
                float hv = hf[i];
                r0 = fmaf(hv, Wo[2 * i + 0], r0);
                r1 = fmaf(hv, Wo[2 * i + 1], r1);
            }
#pragma unroll
            for (int off = 16; off >= 1; off >>= 1) {
                r0 += __shfl_xor_sync(0xffffffffu, r0, off);
                r1 += __shfl_xor_sync(0xffffffffu, r1, off);
            }
            if (l == 0) { s_red[w] = r0; s_red[8 + w] = r1; }
            bar1();
            if (tid == 0) {
                float s0 = 0.f, s1 = 0.f;
#pragma unroll
                for (int ww = 0; ww < 8; ++ww) { s0 += s_red[ww]; s1 += s_red[8 + ww]; }
                out[0] = s0 + bo[0];
                out[1] = s1 + bo[1];
            }
        }
    }
}

extern "C" void kernel_launch(void* const* d_in, const int* in_sizes, int n_in,
                              void* d_out, int out_size) {
    const float* x  = (const float*)d_in[0];
    const float* h0 = (const float*)d_in[1];
    const float* Ws = (const float*)d_in[2];
    const float* bs = (const float*)d_in[3];
    const float* Wo = (const float*)d_in[4];
    const float* bo = (const float*)d_in[5];
    float* out = (float*)d_out;

    static bool attr_set = false;
    if (!attr_set) {
        cudaFuncSetAttribute(pg_seq, cudaFuncAttributeMaxDynamicSharedMemorySize,
                             D * SLOT_BYTES + 1024);
        attr_set = true;
    }

    pg_init<<<1, 128>>>();
    pg_xpart<<<T * 8, 256>>>(x, Ws, bs);
    pg_seq<<<NC, NTH2, D * SLOT_BYTES + 1024>>>(h0, Ws, Wo, bo, out);
}

// round 4
// speedup vs baseline: 1.7453x; 1.2317x over previous
#include <cuda_runtime.h>
#include <math.h>

#define T      128
#define F      512
#define H      1024
#define RZ     1536
#define CPB    8
#define NC     128
#define NTH    384           // 256 consumers + 128 producers
#define D      4
#define SLOT_BYTES (RZ * CPB * 4)     // 49152
#define SLOT_WORDS (RZ * CPB)

__device__ float    g_h[T * H];
__device__ unsigned g_cnt[T];

__global__ void pg_init() {
    if (threadIdx.x < T) g_cnt[threadIdx.x] = 0u;
}

__device__ __forceinline__ unsigned ld_acq(const unsigned* p) {
    unsigned v;
    asm volatile("ld.global.acquire.gpu.u32 %0, [%1];" : "=r"(v) : "l"(p) : "memory");
    return v;
}
__device__ __forceinline__ void red_rel(unsigned* p, unsigned v) {
    asm volatile("red.release.gpu.global.add.u32 [%0], %1;" :: "l"(p), "r"(v) : "memory");
}
__device__ __forceinline__ void cp_async16(unsigned saddr, const void* gaddr) {
    asm volatile("cp.async.cg.shared.global [%0], [%1], 16;" :: "r"(saddr), "l"(gaddr));
}
__device__ __forceinline__ void cp_commit() { asm volatile("cp.async.commit_group;"); }
template<int N> __device__ __forceinline__ void cp_waitg() {
    asm volatile("cp.async.wait_group %0;" :: "n"(N));
}
__device__ __forceinline__ void bar1() {     // consumers only (256 threads)
    asm volatile("bar.sync 1, 256;" ::: "memory");
}

__global__ void __launch_bounds__(NTH, 1) pg_fused(
    const float* __restrict__ x,    // (1, T, F)
    const float* __restrict__ h0,   // (H,)
    const float* __restrict__ Ws,   // (T, RZ, H)
    const float* __restrict__ bs,   // (T, H)
    const float* __restrict__ Wo,   // (H, 2)
    const float* __restrict__ bo,   // (2,)
    float* __restrict__ out)        // [actors(2), h_final(H)]
{
    extern __shared__ char sm[];
    float* s_w   = (float*)sm;                        // D x 48KB z-tiles
    float* s_red = (float*)(sm + D * SLOT_BYTES);     // 64
    int*   s_full = (int*)(s_red + 64);               // D
    volatile int* s_consumed = (volatile int*)(s_full + D);

    const int tid = threadIdx.x;
    const int cg  = blockIdx.x;
    unsigned sbase = (unsigned)__cvta_generic_to_shared(s_w);

    if (tid == 0) {
        for (int i = 0; i < D; ++i) s_full[i] = 0;
        *s_consumed = 0;
    }
    __syncthreads();

    if (tid >= 256) {
        // ================= producers: stream full z-tiles =================
        const int pt = tid - 256;                      // 0..127
        const float* gcols = Ws + (size_t)cg * CPB;
        for (int t = 0; t < T; ++t) {
            while (*s_consumed < t - (D - 1)) { }
            unsigned sb = sbase + (unsigned)(t % D) * SLOT_BYTES;
            const float* gb = gcols + (size_t)t * RZ * H;
#pragma unroll
            for (int i = 0; i < 24; ++i) {
                int n   = i * 128 + pt;                // 0..3071
                int row = n >> 1;
                int cc  = n & 1;
                unsigned soff = sb + (unsigned)(row * 32 + ((cc ^ ((row >> 2) & 1)) << 4));
                cp_async16(soff, (const void*)(gb + (size_t)row * H + cc * 4));
            }
            cp_commit();
            if (t >= 2) {
                cp_waitg<2>();
                __threadfence_block();
                atomicAdd(&s_full[(t - 2) % D], 1);
            }
        }
        cp_waitg<1>(); __threadfence_block(); atomicAdd(&s_full[(T - 2) % D], 1);
        cp_waitg<0>(); __threadfence_block(); atomicAdd(&s_full[(T - 1) % D], 1);
    } else {
        // ================= consumers =================
        const int w = tid >> 5, l = tid & 31;
        for (int t = 0; t < T; ++t) {
            const int slot = t % D;
            float bval = 0.f;
            if (tid < 8) bval = __ldg(&bs[t * H + cg * CPB + tid]);

            // ---- tile ready? (producers run ahead; rarely blocks) ----
            if (tid == 0) {
                while (((volatile int*)s_full)[slot] != 128) { }
            }
            bar1();

            const float* wslot = s_w + slot * SLOT_WORDS;
            float acc[8];
#pragma unroll
            for (int j = 0; j < 8; ++j) acc[j] = 0.f;

            // ---- x-part (rows 0..511): independent of h, fills the wait ----
#pragma unroll
            for (int i = 0; i < 2; ++i) {
                int r = w * 64 + i * 32 + l;
                float zv = __ldg(&x[t * F + r]);
                int sw = (r >> 2) & 1;
                float4 c0 = *(const float4*)(wslot + r * 8 + sw * 4);
                float4 c1 = *(const float4*)(wslot + r * 8 + (sw ^ 1) * 4);
                acc[0] = fmaf(zv, c0.x, acc[0]); acc[1] = fmaf(zv, c0.y, acc[1]);
                acc[2] = fmaf(zv, c0.z, acc[2]); acc[3] = fmaf(zv, c0.w, acc[3]);
                acc[4] = fmaf(zv, c1.x, acc[4]); acc[5] = fmaf(zv, c1.y, acc[5]);
                acc[6] = fmaf(zv, c1.z, acc[6]); acc[7] = fmaf(zv, c1.w, acc[7]);
            }

            // ---- acquire h_{t-1} ----
            if (tid == 0 && t > 0) {
                while (ld_acq(&g_cnt[t - 1]) != (unsigned)NC) { }
            }
            bar1();

            const float* hp = (t == 0) ? h0 : (g_h + (size_t)(t - 1) * H);
            float zv2[4];
#pragma unroll
            for (int i = 0; i < 4; ++i)                 // issue all 4 LDGs first
                zv2[i] = hp[w * 128 + i * 32 + l];
#pragma unroll
            for (int i = 0; i < 4; ++i) {
                int r = F + w * 128 + i * 32 + l;
                int sw = (r >> 2) & 1;
                float4 c0 = *(const float4*)(wslot + r * 8 + sw * 4);
                float4 c1 = *(const float4*)(wslot + r * 8 + (sw ^ 1) * 4);
                float zv = zv2[i];
                acc[0] = fmaf(zv, c0.x, acc[0]); acc[1] = fmaf(zv, c0.y, acc[1]);
                acc[2] = fmaf(zv, c0.z, acc[2]); acc[3] = fmaf(zv, c0.w, acc[3]);
                acc[4] = fmaf(zv, c1.x, acc[4]); acc[5] = fmaf(zv, c1.y, acc[5]);
                acc[6] = fmaf(zv, c1.z, acc[6]); acc[7] = fmaf(zv, c1.w, acc[7]);
            }

            // ---- reduce over 32 lanes per warp ----
#pragma unroll
            for (int off = 16; off >= 1; off >>= 1)
#pragma unroll
                for (int j = 0; j < 8; ++j)
                    acc[j] += __shfl_xor_sync(0xffffffffu, acc[j], off);
            if (l == 0) {
#pragma unroll
                for (int j = 0; j < 8; ++j) s_red[w * 8 + j] = acc[j];
            }
            bar1();                                   // slot fully consumed here

            if (tid == 0) {                           // recycle the slot
                s_full[slot] = 0;
                __threadfence_block();
                *s_consumed = t + 1;
            }
            // warp 0 finishes the step: combine, tanh, store, release
            if (tid < 8) {
                float s = bval;
#pragma unroll
                for (int ww = 0; ww < 8; ++ww) s += s_red[ww * 8 + tid];
                float hv = tanhf(s);
                int col = cg * CPB + tid;
                g_h[(size_t)t * H + col] = hv;
                if (t == T - 1) out[2 + col] = hv;
            }
            __syncwarp(0xffffffffu);                  // order stores before release
            if (tid == 0) red_rel(&g_cnt[t], 1u);     // ONE atomic per CTA
        }

        // ================= actor head (CTA 0) =================
        if (cg == 0) {
            if (tid == 0) while (ld_acq(&g_cnt[T - 1]) != (unsigned)NC) { }
            bar1();
            const float* hf = g_h + (size_t)(T - 1) * H;
            float r0 = 0.f, r1 = 0.f;
            for (int i = tid; i < H; i += 256) {
                float hv = hf[i];
                r0 = fmaf(hv, Wo[2 * i + 0], r0);
                r1 = fmaf(hv, Wo[2 * i + 1], r1);
            }
#pragma unroll
            for (int off = 16; off >= 1; off >>= 1) {
                r0 += __shfl_xor_sync(0xffffffffu, r0, off);
                r1 += __shfl_xor_sync(0xffffffffu, r1, off);
            }
            if (l == 0) { s_red[w] = r0; s_red[8 + w] = r1; }
            bar1();
            if (tid == 0) {
                float s0 = 0.f, s1 = 0.f;
#pragma unroll
                for (int ww = 0; ww < 8; ++ww) { s0 += s_red[ww]; s1 += s_red[8 + ww]; }
                out[0] = s0 + bo[0];
                out[1] = s1 + bo[1];
            }
        }
    }
}

extern "C" void kernel_launch(void* const* d_in, const int* in_sizes, int n_in,
                              void* d_out, int out_size) {
    const float* x  = (const float*)d_in[0];
    const float* h0 = (const float*)d_in[1];
    const float* Ws = (const float*)d_in[2];
    const float* bs = (const float*)d_in[3];
    const float* Wo = (const float*)d_in[4];
    const float* bo = (const float*)d_in[5];
    float* out = (float*)d_out;

    static bool attr_set = false;
    if (!attr_set) {
        cudaFuncSetAttribute(pg_fused, cudaFuncAttributeMaxDynamicSharedMemorySize,
                             D * SLOT_BYTES + 1024);
        attr_set = true;
    }

    pg_init<<<1, 128>>>();
    pg_fused<<<NC, NTH, D * SLOT_BYTES + 1024>>>(x, h0, Ws, bs, Wo, bo, out);
}

// round 7
// speedup vs baseline: 1.8632x; 1.0676x over previous
#include <cuda_runtime.h>
#include <math.h>

#define T      128
#define F      512
#define H      1024
#define RZ     1536
#define CPB    8
#define NC     128           // compute CTAs
#define NPF    20            // prefetch CTAs (spare SMs)
#define NTH    384           // 256 consumers + 128 producers
#define D      4
#define LOOKAHEAD 12         // steps of L2 prefetch distance (76 MB in L2)
#define SLOT_BYTES (RZ * CPB * 4)     // 49152
#define SLOT_WORDS (RZ * CPB)
#define STEP_LINES (RZ * H * 4 / 128) // 49152 lines of 128B per step

__device__ float    g_h[T * H];
__device__ unsigned g_cnt[T];

__global__ void pg_init() {
    if (threadIdx.x < T) g_cnt[threadIdx.x] = 0u;
}

__device__ __forceinline__ unsigned ld_acq(const unsigned* p) {
    unsigned v;
    asm volatile("ld.global.acquire.gpu.u32 %0, [%1];" : "=r"(v) : "l"(p) : "memory");
    return v;
}
__device__ __forceinline__ void red_rel(unsigned* p, unsigned v) {
    asm volatile("red.release.gpu.global.add.u32 [%0], %1;" :: "l"(p), "r"(v) : "memory");
}
__device__ __forceinline__ void prefetch_l2(const void* p) {
    asm volatile("prefetch.global.L2 [%0];" :: "l"(p));
}
__device__ __forceinline__ void cp_async16(unsigned saddr, const void* gaddr) {
    asm volatile("cp.async.cg.shared.global [%0], [%1], 16;" :: "r"(saddr), "l"(gaddr));
}
__device__ __forceinline__ void cp_commit() { asm volatile("cp.async.commit_group;"); }
template<int N> __device__ __forceinline__ void cp_waitg() {
    asm volatile("cp.async.wait_group %0;" :: "n"(N));
}
__device__ __forceinline__ void bar1() {     // consumers only (256 threads)
    asm volatile("bar.sync 1, 256;" ::: "memory");
}

__global__ void __launch_bounds__(NTH, 1) pg_fused(
    const float* __restrict__ x,    // (1, T, F)
    const float* __restrict__ h0,   // (H,)
    const float* __restrict__ Ws,   // (T, RZ, H)
    const float* __restrict__ bs,   // (T, H)
    const float* __restrict__ Wo,   // (H, 2)
    const float* __restrict__ bo,   // (2,)
    float* __restrict__ out)        // [actors(2), h_final(H)]
{
    extern __shared__ char sm[];
    const int tid = threadIdx.x;

    // ================= prefetch CTAs: keep DRAM streaming ahead =================
    if (blockIdx.x >= NC) {
        const int p  = blockIdx.x - NC;              // 0..19
        const int gt = p * NTH + tid;                // 0..7679
        for (int t = 0; t < T; ++t) {
            if (t >= LOOKAHEAD) {
                if (tid == 0) {
                    while (ld_acq(&g_cnt[t - LOOKAHEAD]) != (unsigned)NC) { }
                }
                __syncthreads();
            }
            const char* base = (const char*)(Ws + (size_t)t * RZ * H);
            for (int line = gt; line < STEP_LINES; line += NPF * NTH)
                prefetch_l2(base + (size_t)line * 128);
        }
        return;
    }

    // ================= compute CTAs: identical to the proven R4 =================
    float* s_w   = (float*)sm;                        // D x 48KB z-tiles
    float* s_red = (float*)(sm + D * SLOT_BYTES);     // 64
    int*   s_full = (int*)(s_red + 64);               // D
    volatile int* s_consumed = (volatile int*)(s_full + D);

    const int cg  = blockIdx.x;
    unsigned sbase = (unsigned)__cvta_generic_to_shared(s_w);

    if (tid == 0) {
        for (int i = 0; i < D; ++i) s_full[i] = 0;
        *s_consumed = 0;
    }
    __syncthreads();

    if (tid >= 256) {
        // ---------------- producers: stream full z-tiles ----------------
        const int pt = tid - 256;                      // 0..127
        const float* gcols = Ws + (size_t)cg * CPB;
        for (int t = 0; t < T; ++t) {
            while (*s_consumed < t - (D - 1)) { }
            unsigned sb = sbase + (unsigned)(t % D) * SLOT_BYTES;
            const float* gb = gcols + (size_t)t * RZ * H;
#pragma unroll
            for (int i = 0; i < 24; ++i) {
                int n   = i * 128 + pt;                // 0..3071
                int row = n >> 1;
                int cc  = n & 1;
                unsigned soff = sb + (unsigned)(row * 32 + ((cc ^ ((row >> 2) & 1)) << 4));
                cp_async16(soff, (const void*)(gb + (size_t)row * H + cc * 4));
            }
            cp_commit();
            if (t >= 2) {
                cp_waitg<2>();
                __threadfence_block();
                atomicAdd(&s_full[(t - 2) % D], 1);
            }
        }
        cp_waitg<1>(); __threadfence_block(); atomicAdd(&s_full[(T - 2) % D], 1);
        cp_waitg<0>(); __threadfence_block(); atomicAdd(&s_full[(T - 1) % D], 1);
    } else {
        // ---------------- consumers ----------------
        const int w = tid >> 5, l = tid & 31;
        for (int t = 0; t < T; ++t) {
            const int slot = t % D;
            float bval = 0.f;
            if (tid < 8) bval = __ldg(&bs[t * H + cg * CPB + tid]);

            // ---- tile ready? ----
            if (tid == 0) {
                while (((volatile int*)s_full)[slot] != 128) { }
            }
            bar1();

            const float* wslot = s_w + slot * SLOT_WORDS;
            float acc[8];
#pragma unroll
            for (int j = 0; j < 8; ++j) acc[j] = 0.f;

            // ---- x-part (rows 0..511): independent of h ----
#pragma unroll
            for (int i = 0; i < 2; ++i) {
                int r = w * 64 + i * 32 + l;
                float zv = __ldg(&x[t * F + r]);
                int sw = (r >> 2) & 1;
                float4 c0 = *(const float4*)(wslot + r * 8 + sw * 4);
                float4 c1 = *(const float4*)(wslot + r * 8 + (sw ^ 1) * 4);
                acc[0] = fmaf(zv, c0.x, acc[0]); acc[1] = fmaf(zv, c0.y, acc[1]);
                acc[2] = fmaf(zv, c0.z, acc[2]); acc[3] = fmaf(zv, c0.w, acc[3]);
                acc[4] = fmaf(zv, c1.x, acc[4]); acc[5] = fmaf(zv, c1.y, acc[5]);
                acc[6] = fmaf(zv, c1.z, acc[6]); acc[7] = fmaf(zv, c1.w, acc[7]);
            }

            // ---- acquire h_{t-1} ----
            if (tid == 0 && t > 0) {
                while (ld_acq(&g_cnt[t - 1]) != (unsigned)NC) { }
            }
            bar1();

            const float* hp = (t == 0) ? h0 : (g_h + (size_t)(t - 1) * H);
            float zv2[4];
#pragma unroll
            for (int i = 0; i < 4; ++i)                 // issue all 4 LDGs first
                zv2[i] = hp[w * 128 + i * 32 + l];
#pragma unroll
            for (int i = 0; i < 4; ++i) {
                int r = F + w * 128 + i * 32 + l;
                int sw = (r >> 2) & 1;
                float4 c0 = *(const float4*)(wslot + r * 8 + sw * 4);
                float4 c1 = *(const float4*)(wslot + r * 8 + (sw ^ 1) * 4);
                float zv = zv2[i];
                acc[0] = fmaf(zv, c0.x, acc[0]); acc[1] = fmaf(zv, c0.y, acc[1]);
                acc[2] = fmaf(zv, c0.z, acc[2]); acc[3] = fmaf(zv, c0.w, acc[3]);
                acc[4] = fmaf(zv, c1.x, acc[4]); acc[5] = fmaf(zv, c1.y, acc[5]);
                acc[6] = fmaf(zv, c1.z, acc[6]); acc[7] = fmaf(zv, c1.w, acc[7]);
            }

            // ---- reduce over 32 lanes per warp ----
#pragma unroll
            for (int off = 16; off >= 1; off >>= 1)
#pragma unroll
                for (int j = 0; j < 8; ++j)
                    acc[j] += __shfl_xor_sync(0xffffffffu, acc[j], off);
            if (l == 0) {
#pragma unroll
                for (int j = 0; j < 8; ++j) s_red[w * 8 + j] = acc[j];
            }
            bar1();                                   // slot fully consumed here

            if (tid == 0) {                           // recycle the slot
                s_full[slot] = 0;
                __threadfence_block();
                *s_consumed = t + 1;
            }
            // warp 0 finishes the step: combine, tanh, store, release
            if (tid < 8) {
                float s = bval;
#pragma unroll
                for (int ww = 0; ww < 8; ++ww) s += s_red[ww * 8 + tid];
                float hv = tanhf(s);
                int col = cg * CPB + tid;
                g_h[(size_t)t * H + col] = hv;
                if (t == T - 1) out[2 + col] = hv;
            }
            __syncwarp(0xffffffffu);                  // order stores before release
            if (tid == 0) red_rel(&g_cnt[t], 1u);     // ONE atomic per CTA
        }

        // ---------------- actor head (CTA 0) ----------------
        if (cg == 0) {
            if (tid == 0) while (ld_acq(&g_cnt[T - 1]) != (unsigned)NC) { }
            bar1();
            const float* hf = g_h + (size_t)(T - 1) * H;
            float r0 = 0.f, r1 = 0.f;
            for (int i = tid; i < H; i += 256) {
                float hv = hf[i];
                r0 = fmaf(hv, Wo[2 * i + 0], r0);
                r1 = fmaf(hv, Wo[2 * i + 1], r1);
            }
#pragma unroll
            for (int off = 16; off >= 1; off >>= 1) {
                r0 += __shfl_xor_sync(0xffffffffu, r0, off);
                r1 += __shfl_xor_sync(0xffffffffu, r1, off);
            }
            if (l == 0) { s_red[w] = r0; s_red[8 + w] = r1; }
            bar1();
            if (tid == 0) {
                float s0 = 0.f, s1 = 0.f;
#pragma unroll
                for (int ww = 0; ww < 8; ++ww) { s0 += s_red[ww]; s1 += s_red[8 + ww]; }
                out[0] = s0 + bo[0];
                out[1] = s1 + bo[1];
            }
        }
    }
}

extern "C" void kernel_launch(void* const* d_in, const int* in_sizes, int n_in,
                              void* d_out, int out_size) {
    const float* x  = (const float*)d_in[0];
    const float* h0 = (const float*)d_in[1];
    const float* Ws = (const float*)d_in[2];
    const float* bs = (const float*)d_in[3];
    const float* Wo = (const float*)d_in[4];
    const float* bo = (const float*)d_in[5];
    float* out = (float*)d_out;

    static bool attr_set = false;
    if (!attr_set) {
        cudaFuncSetAttribute(pg_fused, cudaFuncAttributeMaxDynamicSharedMemorySize,
                             D * SLOT_BYTES + 1024);
        attr_set = true;
    }

    pg_init<<<1, 128>>>();
    pg_fused<<<NC + NPF, NTH, D * SLOT_BYTES + 1024>>>(x, h0, Ws, bs, Wo, bo, out);
}